// round 14
// baseline (speedup 1.0000x reference)
#include <cuda_runtime.h>
#include <math.h>

// Problem-fixed sizes (from reference setup_inputs)
#define NMAX 100000
#define EMAX 1600000
#define CAP  128        // per-node adjacency bucket capacity (Poisson(32) -> safe)

// ---- device-global scratch (no runtime allocation allowed) ----
__device__ float g_h1[NMAX * 32];        // FCNN_one(x)  12.8 MB
__device__ float g_h2[NMAX * 32];        // FCNN_two(x)  12.8 MB
__device__ int   g_cnt[NMAX];            // per-node incident count (zero-init;
                                         // re-zeroed at start of gather_kernel)
__device__ int2  g_adj[NMAX * CAP];      // (.x = neighbor, .y = edge id) 102.4 MB
__device__ int   g_is64;                 // 1 if edge_index is int64, 0 if int32

// ---- packed f32x2 helpers (sm_103a FFMA2 — PTX-only, doubles fp32 FMA tput) ----
__device__ __forceinline__ unsigned long long pk2(float lo, float hi) {
    unsigned long long r;
    asm("mov.b64 %0, {%1, %2};" : "=l"(r)
        : "r"(__float_as_uint(lo)), "r"(__float_as_uint(hi)));
    return r;
}
__device__ __forceinline__ void fma2(unsigned long long& d,
                                     unsigned long long a, unsigned long long b) {
    asm("fma.rn.f32x2 %0, %1, %2, %0;" : "+l"(d) : "l"(a), "l"(b));
}
__device__ __forceinline__ float2 upk2(unsigned long long v) {
    unsigned int lo, hi;
    asm("mov.b64 {%0, %1}, %2;" : "=r"(lo), "=r"(hi) : "l"(v));
    return make_float2(__uint_as_float(lo), __uint_as_float(hi));
}

// ----------------------------------------------------------------------------
// 0) detect edge_index dtype. int64 LE => every odd 32-bit word is 0
//    (ids < 2^32); 256 consecutive zero high-words from random int32 ids in
//    [0,100000) is impossible.
// ----------------------------------------------------------------------------
__global__ void detect_kernel(const void* __restrict__ ei, int E) {
    __shared__ int s_bad;
    if (threadIdx.x == 0) s_bad = 0;
    __syncthreads();
    int n = E < 256 ? E : 256;
    const int* w = (const int*)ei;
    if ((int)threadIdx.x < n && w[2 * threadIdx.x + 1] != 0) s_bad = 1;
    __syncthreads();
    if (threadIdx.x == 0) g_is64 = s_bad ? 0 : 1;
}

// ----------------------------------------------------------------------------
// 1) FUSED fill + FCNN kernel. Interleaved block roles:
//      even blockIdx -> one FCNN tile (128 nodes)      [FMA/LDS-bound]
//      odd  blockIdx -> one fill slice (2048 edges)    [atomic/memory-bound]
//    The two phases are data-independent; interleaving co-schedules them on
//    each SM so complementary pipes overlap instead of serializing
//    (~155us combined when serialized across R9/R11/R13 runs).
// ----------------------------------------------------------------------------
#define FCNN_SMEM_FLOATS (32 * 129 + 4096 + 128 + 32 + 128 * 129)
#define FCNN_SMEM_BYTES  (FCNN_SMEM_FLOATS * 4)
#define FILL_SLICE 2048

__device__ __forceinline__ void fill_slice_body(const void* __restrict__ ei,
                                                int E, int N, int slice) {
    const int t = threadIdx.x;
    const int base = slice * FILL_SLICE;
    const bool is64 = (g_is64 != 0);
    #pragma unroll
    for (int k = 0; k < FILL_SLICE / 256; ++k) {     // 8 independent chains/thread
        int e = base + k * 256 + t;
        if (e >= E) break;
        int u, v;
        if (is64) {
            const long long* p = (const long long*)ei;
            u = (int)__ldg(&p[e]); v = (int)__ldg(&p[E + e]);
        } else {
            const int* p = (const int*)ei;
            u = __ldg(&p[e]); v = __ldg(&p[E + e]);
        }
        if ((unsigned)u >= (unsigned)N || (unsigned)v >= (unsigned)N) continue;
        int p1 = atomicAdd(&g_cnt[u], 1);
        if (p1 < CAP) g_adj[u * CAP + p1] = make_int2(v, e);
        int q1 = atomicAdd(&g_cnt[v], 1);
        if (q1 < CAP) g_adj[v * CAP + q1] = make_int2(u, e);
    }
}

__global__ void __launch_bounds__(256, 2) fused_kernel(
    const float* __restrict__ x,
    const float* __restrict__ W1a, const float* __restrict__ b1a,
    const float* __restrict__ W2a, const float* __restrict__ b2a,
    const float* __restrict__ W1b, const float* __restrict__ b1b,
    const float* __restrict__ W2b, const float* __restrict__ b2b,
    const void* __restrict__ ei,
    int N, int E, int nf, int ns)
{
    const int b    = blockIdx.x;
    const int half = b >> 1;

    if (b & 1) {                       // ---- fill role ----
        if (half < ns) fill_slice_body(ei, E, N, half);
        return;
    }
    if (half >= nf) return;            // ---- fcnn role ----

    extern __shared__ float sm[];
    float* xs  = sm;                 // [32][129]  x transposed: xs[d][m]
    float* wb  = xs + 32 * 129;      // 4096 : W1 (stage1) then W2 (stage2)
    float* bb1 = wb + 4096;          // 128
    float* bb2 = bb1 + 128;          // 32
    float* hid = bb2 + 32;           // [128][129]

    const int t    = threadIdx.x;
    const int tm   = t & 15;         // m-group
    const int tq   = t >> 4;         // k-group (stage1) / n-group (stage2)
    const int base = half * 128;

    for (int idx = t; idx < 128 * 32; idx += 256) {
        int m = idx >> 5, d = idx & 31;
        int node = base + m;
        xs[d * 129 + m] = (node < N) ? x[node * 32 + d] : 0.f;
    }

    for (int f = 0; f < 2; ++f) {
        const float* W1 = f ? W1b : W1a;
        const float* B1 = f ? b1b : b1a;
        const float* W2 = f ? W2b : W2a;
        const float* B2 = f ? b2b : b2a;

        __syncthreads();
        for (int idx = t; idx < 4096; idx += 256) wb[idx] = W1[idx];
        if (t < 128) bb1[t] = B1[t];
        if (t < 32)  bb2[t] = B2[t];
        __syncthreads();

        // ---- stage 1: hid = relu(xs^T @ W1 + b1), f32x2 over column pairs ----
        unsigned long long acc[8][4];
        #pragma unroll
        for (int j = 0; j < 4; ++j) {
            unsigned long long bbv = pk2(bb1[tq + 32 * j], bb1[tq + 32 * j + 16]);
            #pragma unroll
            for (int i = 0; i < 8; ++i) acc[i][j] = bbv;
        }
        #pragma unroll 4
        for (int d = 0; d < 32; ++d) {
            unsigned long long ap[8], bp[4];
            #pragma unroll
            for (int i = 0; i < 8; ++i) {
                float a = xs[d * 129 + tm + 16 * i];
                ap[i] = pk2(a, a);
            }
            #pragma unroll
            for (int j = 0; j < 4; ++j)
                bp[j] = pk2(wb[d * 128 + tq + 32 * j],
                            wb[d * 128 + tq + 32 * j + 16]);
            #pragma unroll
            for (int i = 0; i < 8; ++i)
                #pragma unroll
                for (int j = 0; j < 4; ++j)
                    fma2(acc[i][j], ap[i], bp[j]);
        }
        __syncthreads();
        #pragma unroll
        for (int i = 0; i < 8; ++i)
            #pragma unroll
            for (int j = 0; j < 4; ++j) {
                float2 v = upk2(acc[i][j]);
                hid[(tm + 16 * i) * 129 + tq + 32 * j]      = fmaxf(v.x, 0.f);
                hid[(tm + 16 * i) * 129 + tq + 32 * j + 16] = fmaxf(v.y, 0.f);
            }
        __syncthreads();

        for (int idx = t; idx < 4096; idx += 256) wb[idx] = W2[idx];
        __syncthreads();

        // ---- stage 2: out = hid @ W2 + b2, f32x2 over column pair (tq,tq+16) ----
        unsigned long long acc2[8];
        {
            unsigned long long bbv = pk2(bb2[tq], bb2[tq + 16]);
            #pragma unroll
            for (int i = 0; i < 8; ++i) acc2[i] = bbv;
        }
        #pragma unroll 4
        for (int d = 0; d < 128; ++d) {
            unsigned long long bp = pk2(wb[d * 32 + tq], wb[d * 32 + tq + 16]);
            #pragma unroll
            for (int i = 0; i < 8; ++i) {
                float av = hid[(tm + 16 * i) * 129 + d];
                unsigned long long ap = pk2(av, av);
                fma2(acc2[i], ap, bp);
            }
        }
        float* H = f ? g_h2 : g_h1;
        #pragma unroll
        for (int i = 0; i < 8; ++i) {
            int node = base + tm + 16 * i;
            if (node < N) {
                float2 v = upk2(acc2[i]);
                H[node * 32 + tq]      = v.x;
                H[node * 32 + tq + 16] = v.y;
            }
        }
    }
}

// ----------------------------------------------------------------------------
// 2) warp-per-node gather + divide + InstanceNorm + residual ReLU (fused).
//    EXACT R9 loop shape (measured 132us; x4 / float2 / two-warp variants all
//    regressed). Counter reset at loop start, off the critical path.
//    agg[i] = (sum_e s_e * h2[nbr]) / (1e-7 + sum_e s_e)  [denominator factored].
// ----------------------------------------------------------------------------
__device__ __forceinline__ float fast_sigmoid(float v) {
    float th;
    asm("tanh.approx.f32 %0, %1;" : "=f"(th) : "f"(0.5f * v));
    return fmaf(0.5f, th, 0.5f);
}

__global__ void __launch_bounds__(256) gather_kernel(
    const float* __restrict__ x,
    const float* __restrict__ ef,
    float* __restrict__ out, int N)
{
    int w    = (blockIdx.x * blockDim.x + threadIdx.x) >> 5;
    int lane = threadIdx.x & 31;
    if (w >= N) return;

    int deg = g_cnt[w];
    if (lane == 0) g_cnt[w] = 0;          // reset for next launch (deterministic)
    if (deg > CAP) deg = CAP;
    const int2* adj = &g_adj[w * CAP];
    float dsum = 0.f, nsum = 0.f;

    int k = 0;
    for (; k + 1 < deg; k += 2) {
        int2 c0 = adj[k];
        int2 c1 = adj[k + 1];
        float s0 = __ldcs(&ef[c0.y * 32 + lane]);
        float s1 = __ldcs(&ef[c1.y * 32 + lane]);
        float h0 = g_h2[c0.x * 32 + lane];
        float h1 = g_h2[c1.x * 32 + lane];
        s0 = fast_sigmoid(s0);
        s1 = fast_sigmoid(s1);
        dsum += s0 + s1;
        nsum = fmaf(s0, h0, nsum);
        nsum = fmaf(s1, h1, nsum);
    }
    if (k < deg) {
        int2 c0 = adj[k];
        float s0 = fast_sigmoid(__ldcs(&ef[c0.y * 32 + lane]));
        dsum += s0;
        nsum = fmaf(s0, g_h2[c0.x * 32 + lane], nsum);
    }

    float h = g_h1[w * 32 + lane] + nsum / (1e-7f + dsum);

    // InstanceNorm over the 32 feature lanes (biased variance, eps=1e-5)
    float mu = h;
    #pragma unroll
    for (int o = 16; o > 0; o >>= 1) mu += __shfl_xor_sync(0xffffffffu, mu, o);
    mu *= (1.f / 32.f);
    float df = h - mu;
    float vv = df * df;
    #pragma unroll
    for (int o = 16; o > 0; o >>= 1) vv += __shfl_xor_sync(0xffffffffu, vv, o);
    vv *= (1.f / 32.f);
    float hn = df * rsqrtf(vv + 1e-5f);

    out[w * 32 + lane] = x[w * 32 + lane] + fmaxf(hn, 0.f);
}

// ----------------------------------------------------------------------------
extern "C" void kernel_launch(void* const* d_in, const int* in_sizes, int n_in,
                              void* d_out, int out_size)
{
    const float* xin = (const float*)d_in[0];
    const float* ef  = (const float*)d_in[1];
    const float* W1a = (const float*)d_in[2];
    const float* b1a = (const float*)d_in[3];
    const float* W2a = (const float*)d_in[4];
    const float* b2a = (const float*)d_in[5];
    const float* W1b = (const float*)d_in[6];
    const float* b1b = (const float*)d_in[7];
    const float* W2b = (const float*)d_in[8];
    const float* b2b = (const float*)d_in[9];
    const void*  ei  = d_in[10];              // int32 or int64 — detected on device
    float* out = (float*)d_out;

    const int N  = in_sizes[0] / 32;
    const int E  = in_sizes[10] / 2;
    const int nf = (N + 127) / 128;                 // fcnn tile blocks
    const int ns = (E + FILL_SLICE - 1) / FILL_SLICE; // fill slice blocks
    const int nb = (nf > ns ? nf : ns) * 2;         // interleaved grid

    cudaFuncSetAttribute(fused_kernel,
                         cudaFuncAttributeMaxDynamicSharedMemorySize,
                         FCNN_SMEM_BYTES);

    detect_kernel<<<1, 256>>>(ei, E);
    fused_kernel <<<nb, 256, FCNN_SMEM_BYTES>>>(
        xin, W1a, b1a, W2a, b2a, W1b, b1b, W2b, b2b, ei, N, E, nf, ns);
    gather_kernel<<<(N + 7) / 8, 256>>>(xin, ef, out, N);
}

// round 15
// speedup vs baseline: 1.0049x; 1.0049x over previous
#include <cuda_runtime.h>
#include <math.h>

// Problem-fixed sizes (from reference setup_inputs)
#define NMAX 100000
#define EMAX 1600000
#define CAP  128        // per-node adjacency bucket capacity (Poisson(32) -> safe)

// ---- device-global scratch (no runtime allocation allowed) ----
__device__ float g_h1[NMAX * 32];        // FCNN_one(x)  12.8 MB
__device__ float g_h2[NMAX * 32];        // FCNN_two(x)  12.8 MB
__device__ int   g_cnt[NMAX];            // per-node incident count (zero-init;
                                         // re-zeroed at start of gather_kernel)
__device__ int2  g_adj[NMAX * CAP];      // (.x = neighbor, .y = edge id) 102.4 MB

// ---- packed f32x2 helpers (sm_103a FFMA2 — PTX-only, doubles fp32 FMA tput) ----
__device__ __forceinline__ unsigned long long pk2(float lo, float hi) {
    unsigned long long r;
    asm("mov.b64 %0, {%1, %2};" : "=l"(r)
        : "r"(__float_as_uint(lo)), "r"(__float_as_uint(hi)));
    return r;
}
__device__ __forceinline__ void fma2(unsigned long long& d,
                                     unsigned long long a, unsigned long long b) {
    asm("fma.rn.f32x2 %0, %1, %2, %0;" : "+l"(d) : "l"(a), "l"(b));
}
__device__ __forceinline__ float2 upk2(unsigned long long v) {
    unsigned int lo, hi;
    asm("mov.b64 {%0, %1}, %2;" : "=r"(lo), "=r"(hi) : "l"(v));
    return make_float2(__uint_as_float(lo), __uint_as_float(hi));
}

// ----------------------------------------------------------------------------
// 1) bucket adjacency fill, 512-edge slices, 2 edges/thread.
//    Dtype self-detection per block: int64 LE => every odd 32-bit word of the
//    index buffer is 0 (ids < 2^32); 256 consecutive zero high-words from
//    random int32 ids in [0,100000) is impossible. Block 0's check hits DRAM,
//    the rest hit L2 (~2KB read). Removes the separate detect launch.
//    g_cnt is zero on entry (zero-init at load; re-zeroed by gather).
// ----------------------------------------------------------------------------
__device__ __forceinline__ void fill_one(const void* ei, bool is64,
                                         int E, int N, int e) {
    int u, v;
    if (is64) {
        const long long* p = (const long long*)ei;
        u = (int)__ldg(&p[e]); v = (int)__ldg(&p[E + e]);
    } else {
        const int* p = (const int*)ei;
        u = __ldg(&p[e]); v = __ldg(&p[E + e]);
    }
    if ((unsigned)u >= (unsigned)N || (unsigned)v >= (unsigned)N) return;
    int p1 = atomicAdd(&g_cnt[u], 1);
    if (p1 < CAP) g_adj[u * CAP + p1] = make_int2(v, e);
    int q1 = atomicAdd(&g_cnt[v], 1);
    if (q1 < CAP) g_adj[v * CAP + q1] = make_int2(u, e);
}

__global__ void fill_kernel(const void* __restrict__ ei, int E, int N) {
    __shared__ int s_bad;
    const int t = threadIdx.x;
    if (t == 0) s_bad = 0;
    __syncthreads();
    int n = E < 256 ? E : 256;
    const int* wd = (const int*)ei;
    if (t < n && wd[2 * t + 1] != 0) s_bad = 1;
    __syncthreads();
    const bool is64 = (s_bad == 0);

    const int base = blockIdx.x * 512;
    int e0 = base + t;
    int e1 = base + 256 + t;
    if (e0 < E) fill_one(ei, is64, E, N, e0);
    if (e1 < E) fill_one(ei, is64, E, N, e1);
}

// ----------------------------------------------------------------------------
// 2) both FCNNs with packed f32x2 FMA.
//    128 nodes/block, 256 threads, strided lane map -> conflict-free smem.
// ----------------------------------------------------------------------------
#define FCNN_SMEM_FLOATS (32 * 129 + 4096 + 128 + 32 + 128 * 129)
#define FCNN_SMEM_BYTES  (FCNN_SMEM_FLOATS * 4)

__global__ void __launch_bounds__(256, 2) fcnn_kernel(
    const float* __restrict__ x,
    const float* __restrict__ W1a, const float* __restrict__ b1a,
    const float* __restrict__ W2a, const float* __restrict__ b2a,
    const float* __restrict__ W1b, const float* __restrict__ b1b,
    const float* __restrict__ W2b, const float* __restrict__ b2b,
    int N)
{
    extern __shared__ float sm[];
    float* xs  = sm;                 // [32][129]  x transposed: xs[d][m]
    float* wb  = xs + 32 * 129;      // 4096 : W1 (stage1) then W2 (stage2)
    float* bb1 = wb + 4096;          // 128
    float* bb2 = bb1 + 128;          // 32
    float* hid = bb2 + 32;           // [128][129]

    const int t    = threadIdx.x;
    const int tm   = t & 15;         // m-group
    const int tq   = t >> 4;         // k-group (stage1) / n-group (stage2)
    const int base = blockIdx.x * 128;

    for (int idx = t; idx < 128 * 32; idx += 256) {
        int m = idx >> 5, d = idx & 31;
        int node = base + m;
        xs[d * 129 + m] = (node < N) ? x[node * 32 + d] : 0.f;
    }

    for (int f = 0; f < 2; ++f) {
        const float* W1 = f ? W1b : W1a;
        const float* B1 = f ? b1b : b1a;
        const float* W2 = f ? W2b : W2a;
        const float* B2 = f ? b2b : b2a;

        __syncthreads();
        for (int idx = t; idx < 4096; idx += 256) wb[idx] = W1[idx];
        if (t < 128) bb1[t] = B1[t];
        if (t < 32)  bb2[t] = B2[t];
        __syncthreads();

        // ---- stage 1: hid = relu(xs^T @ W1 + b1), f32x2 over column pairs ----
        unsigned long long acc[8][4];
        #pragma unroll
        for (int j = 0; j < 4; ++j) {
            unsigned long long b = pk2(bb1[tq + 32 * j], bb1[tq + 32 * j + 16]);
            #pragma unroll
            for (int i = 0; i < 8; ++i) acc[i][j] = b;
        }
        #pragma unroll 4
        for (int d = 0; d < 32; ++d) {
            unsigned long long ap[8], bp[4];
            #pragma unroll
            for (int i = 0; i < 8; ++i) {
                float a = xs[d * 129 + tm + 16 * i];
                ap[i] = pk2(a, a);
            }
            #pragma unroll
            for (int j = 0; j < 4; ++j)
                bp[j] = pk2(wb[d * 128 + tq + 32 * j],
                            wb[d * 128 + tq + 32 * j + 16]);
            #pragma unroll
            for (int i = 0; i < 8; ++i)
                #pragma unroll
                for (int j = 0; j < 4; ++j)
                    fma2(acc[i][j], ap[i], bp[j]);
        }
        __syncthreads();
        #pragma unroll
        for (int i = 0; i < 8; ++i)
            #pragma unroll
            for (int j = 0; j < 4; ++j) {
                float2 v = upk2(acc[i][j]);
                hid[(tm + 16 * i) * 129 + tq + 32 * j]      = fmaxf(v.x, 0.f);
                hid[(tm + 16 * i) * 129 + tq + 32 * j + 16] = fmaxf(v.y, 0.f);
            }
        __syncthreads();

        for (int idx = t; idx < 4096; idx += 256) wb[idx] = W2[idx];
        __syncthreads();

        // ---- stage 2: out = hid @ W2 + b2, f32x2 over column pair (tq,tq+16) ----
        unsigned long long acc2[8];
        {
            unsigned long long b = pk2(bb2[tq], bb2[tq + 16]);
            #pragma unroll
            for (int i = 0; i < 8; ++i) acc2[i] = b;
        }
        #pragma unroll 4
        for (int d = 0; d < 128; ++d) {
            unsigned long long bp = pk2(wb[d * 32 + tq], wb[d * 32 + tq + 16]);
            #pragma unroll
            for (int i = 0; i < 8; ++i) {
                float av = hid[(tm + 16 * i) * 129 + d];
                unsigned long long ap = pk2(av, av);
                fma2(acc2[i], ap, bp);
            }
        }
        float* H = f ? g_h2 : g_h1;
        #pragma unroll
        for (int i = 0; i < 8; ++i) {
            int node = base + tm + 16 * i;
            if (node < N) {
                float2 v = upk2(acc2[i]);
                H[node * 32 + tq]      = v.x;
                H[node * 32 + tq + 16] = v.y;
            }
        }
    }
}

// ----------------------------------------------------------------------------
// 3) warp-per-node gather + divide + InstanceNorm + residual ReLU (fused).
//    EXACT R9 configuration: x2 loop, reset-at-start, __ldcs on ef only.
//    (Measured 132us; x4 unroll, half-warp float2, and two-warp-split variants
//    all regressed 1.8-4x — this loop shape is locally optimal.)
//    agg[i] = (sum_e s_e * h2[nbr]) / (1e-7 + sum_e s_e)  [denominator factored].
// ----------------------------------------------------------------------------
__device__ __forceinline__ float fast_sigmoid(float v) {
    float th;
    asm("tanh.approx.f32 %0, %1;" : "=f"(th) : "f"(0.5f * v));
    return fmaf(0.5f, th, 0.5f);
}

__global__ void __launch_bounds__(256) gather_kernel(
    const float* __restrict__ x,
    const float* __restrict__ ef,
    float* __restrict__ out, int N)
{
    int w    = (blockIdx.x * blockDim.x + threadIdx.x) >> 5;
    int lane = threadIdx.x & 31;
    if (w >= N) return;

    int deg = g_cnt[w];
    if (lane == 0) g_cnt[w] = 0;          // reset for next launch (deterministic)
    if (deg > CAP) deg = CAP;
    const int2* adj = &g_adj[w * CAP];
    float dsum = 0.f, nsum = 0.f;

    int k = 0;
    for (; k + 1 < deg; k += 2) {
        int2 c0 = adj[k];
        int2 c1 = adj[k + 1];
        float s0 = __ldcs(&ef[c0.y * 32 + lane]);
        float s1 = __ldcs(&ef[c1.y * 32 + lane]);
        float h0 = g_h2[c0.x * 32 + lane];
        float h1 = g_h2[c1.x * 32 + lane];
        s0 = fast_sigmoid(s0);
        s1 = fast_sigmoid(s1);
        dsum += s0 + s1;
        nsum = fmaf(s0, h0, nsum);
        nsum = fmaf(s1, h1, nsum);
    }
    if (k < deg) {
        int2 c0 = adj[k];
        float s0 = fast_sigmoid(__ldcs(&ef[c0.y * 32 + lane]));
        dsum += s0;
        nsum = fmaf(s0, g_h2[c0.x * 32 + lane], nsum);
    }

    float h = g_h1[w * 32 + lane] + nsum / (1e-7f + dsum);

    // InstanceNorm over the 32 feature lanes (biased variance, eps=1e-5)
    float mu = h;
    #pragma unroll
    for (int o = 16; o > 0; o >>= 1) mu += __shfl_xor_sync(0xffffffffu, mu, o);
    mu *= (1.f / 32.f);
    float df = h - mu;
    float vv = df * df;
    #pragma unroll
    for (int o = 16; o > 0; o >>= 1) vv += __shfl_xor_sync(0xffffffffu, vv, o);
    vv *= (1.f / 32.f);
    float hn = df * rsqrtf(vv + 1e-5f);

    out[w * 32 + lane] = x[w * 32 + lane] + fmaxf(hn, 0.f);
}

// ----------------------------------------------------------------------------
extern "C" void kernel_launch(void* const* d_in, const int* in_sizes, int n_in,
                              void* d_out, int out_size)
{
    const float* xin = (const float*)d_in[0];
    const float* ef  = (const float*)d_in[1];
    const float* W1a = (const float*)d_in[2];
    const float* b1a = (const float*)d_in[3];
    const float* W2a = (const float*)d_in[4];
    const float* b2a = (const float*)d_in[5];
    const float* W1b = (const float*)d_in[6];
    const float* b1b = (const float*)d_in[7];
    const float* W2b = (const float*)d_in[8];
    const float* b2b = (const float*)d_in[9];
    const void*  ei  = d_in[10];              // int32 or int64 — self-detected
    float* out = (float*)d_out;

    const int N = in_sizes[0] / 32;
    const int E = in_sizes[10] / 2;

    cudaFuncSetAttribute(fcnn_kernel,
                         cudaFuncAttributeMaxDynamicSharedMemorySize,
                         FCNN_SMEM_BYTES);

    fill_kernel  <<<(E + 511) / 512, 256>>>(ei, E, N);
    fcnn_kernel  <<<(N + 127) / 128, 256, FCNN_SMEM_BYTES>>>(
        xin, W1a, b1a, W2a, b2a, W1b, b1b, W2b, b2b, N);
    gather_kernel<<<(N + 7) / 8, 256>>>(xin, ef, out, N);
}

// round 16
// speedup vs baseline: 2.0229x; 2.0131x over previous
#include <cuda_runtime.h>
#include <math.h>

// Problem-fixed sizes (from reference setup_inputs)
#define NMAX 100000
#define EMAX 1600000
#define CAP  128        // per-node adjacency bucket capacity (Poisson(32) -> safe)

// ---- device-global scratch (no runtime allocation allowed) ----
__device__ float g_h1[NMAX * 32];        // FCNN_one(x)  12.8 MB
__device__ float g_h2[NMAX * 32];        // FCNN_two(x)  12.8 MB
__device__ int   g_cnt[NMAX];            // per-node incident count
__device__ int2  g_adj[NMAX * CAP];      // (.x = neighbor, .y = edge id) 102.4 MB
__device__ int   g_is64;                 // 1 if edge_index is int64, 0 if int32

// ---- packed f32x2 helpers (sm_103a FFMA2 — PTX-only, doubles fp32 FMA tput) ----
__device__ __forceinline__ unsigned long long pk2(float lo, float hi) {
    unsigned long long r;
    asm("mov.b64 %0, {%1, %2};" : "=l"(r)
        : "r"(__float_as_uint(lo)), "r"(__float_as_uint(hi)));
    return r;
}
__device__ __forceinline__ void fma2(unsigned long long& d,
                                     unsigned long long a, unsigned long long b) {
    asm("fma.rn.f32x2 %0, %1, %2, %0;" : "+l"(d) : "l"(a), "l"(b));
}
__device__ __forceinline__ float2 upk2(unsigned long long v) {
    unsigned int lo, hi;
    asm("mov.b64 {%0, %1}, %2;" : "=r"(lo), "=r"(hi) : "l"(v));
    return make_float2(__uint_as_float(lo), __uint_as_float(hi));
}

// ----------------------------------------------------------------------------
// 1) zero counters + detect edge_index dtype (block 0).
//    int64 LE => every odd 32-bit word is 0 (ids < 2^32); 256 consecutive
//    zero high-words from random int32 ids in [0,100000) is impossible.
//    NOTE: this per-launch zero of g_cnt is load-bearing — resetting g_cnt
//    inside gather's prologue instead was the common factor in every 600+us
//    regression (R10/R12/R14/R15). Do not move it.
// ----------------------------------------------------------------------------
__global__ void init_kernel(const void* __restrict__ ei, int E, int N) {
    int i = blockIdx.x * blockDim.x + threadIdx.x;
    if (i < N) g_cnt[i] = 0;
    if (blockIdx.x == 0) {
        __shared__ int s_bad;
        if (threadIdx.x == 0) s_bad = 0;
        __syncthreads();
        int n = E < 256 ? E : 256;
        const int* w = (const int*)ei;
        if ((int)threadIdx.x < n && w[2 * threadIdx.x + 1] != 0) s_bad = 1;
        __syncthreads();
        if (threadIdx.x == 0) g_is64 = s_bad ? 0 : 1;
    }
}

// ----------------------------------------------------------------------------
// 2) single-pass bucket adjacency fill (both directions per edge)
// ----------------------------------------------------------------------------
__global__ void fill_kernel(const void* __restrict__ ei, int E, int N) {
    int e = blockIdx.x * blockDim.x + threadIdx.x;
    if (e >= E) return;
    int u, v;
    if (g_is64) {
        const long long* p = (const long long*)ei;
        u = (int)p[e]; v = (int)p[E + e];
    } else {
        const int* p = (const int*)ei;
        u = p[e]; v = p[E + e];
    }
    if ((unsigned)u >= (unsigned)N || (unsigned)v >= (unsigned)N) return;
    int p1 = atomicAdd(&g_cnt[u], 1);
    if (p1 < CAP) g_adj[u * CAP + p1] = make_int2(v, e);
    int q1 = atomicAdd(&g_cnt[v], 1);
    if (q1 < CAP) g_adj[v * CAP + q1] = make_int2(u, e);
}

// ----------------------------------------------------------------------------
// 3) both FCNNs with packed f32x2 FMA.
//    128 nodes/block, 256 threads, strided lane map -> conflict-free smem.
// ----------------------------------------------------------------------------
#define FCNN_SMEM_FLOATS (32 * 129 + 4096 + 128 + 32 + 128 * 129)
#define FCNN_SMEM_BYTES  (FCNN_SMEM_FLOATS * 4)

__global__ void __launch_bounds__(256, 2) fcnn_kernel(
    const float* __restrict__ x,
    const float* __restrict__ W1a, const float* __restrict__ b1a,
    const float* __restrict__ W2a, const float* __restrict__ b2a,
    const float* __restrict__ W1b, const float* __restrict__ b1b,
    const float* __restrict__ W2b, const float* __restrict__ b2b,
    int N)
{
    extern __shared__ float sm[];
    float* xs  = sm;                 // [32][129]  x transposed: xs[d][m]
    float* wb  = xs + 32 * 129;      // 4096 : W1 (stage1) then W2 (stage2)
    float* bb1 = wb + 4096;          // 128
    float* bb2 = bb1 + 128;          // 32
    float* hid = bb2 + 32;           // [128][129]

    const int t    = threadIdx.x;
    const int tm   = t & 15;         // m-group
    const int tq   = t >> 4;         // k-group (stage1) / n-group (stage2)
    const int base = blockIdx.x * 128;

    for (int idx = t; idx < 128 * 32; idx += 256) {
        int m = idx >> 5, d = idx & 31;
        int node = base + m;
        xs[d * 129 + m] = (node < N) ? x[node * 32 + d] : 0.f;
    }

    for (int f = 0; f < 2; ++f) {
        const float* W1 = f ? W1b : W1a;
        const float* B1 = f ? b1b : b1a;
        const float* W2 = f ? W2b : W2a;
        const float* B2 = f ? b2b : b2a;

        __syncthreads();
        for (int idx = t; idx < 4096; idx += 256) wb[idx] = W1[idx];
        if (t < 128) bb1[t] = B1[t];
        if (t < 32)  bb2[t] = B2[t];
        __syncthreads();

        // ---- stage 1: hid = relu(xs^T @ W1 + b1), f32x2 over column pairs ----
        unsigned long long acc[8][4];
        #pragma unroll
        for (int j = 0; j < 4; ++j) {
            unsigned long long b = pk2(bb1[tq + 32 * j], bb1[tq + 32 * j + 16]);
            #pragma unroll
            for (int i = 0; i < 8; ++i) acc[i][j] = b;
        }
        #pragma unroll 4
        for (int d = 0; d < 32; ++d) {
            unsigned long long ap[8], bp[4];
            #pragma unroll
            for (int i = 0; i < 8; ++i) {
                float a = xs[d * 129 + tm + 16 * i];
                ap[i] = pk2(a, a);
            }
            #pragma unroll
            for (int j = 0; j < 4; ++j)
                bp[j] = pk2(wb[d * 128 + tq + 32 * j],
                            wb[d * 128 + tq + 32 * j + 16]);
            #pragma unroll
            for (int i = 0; i < 8; ++i)
                #pragma unroll
                for (int j = 0; j < 4; ++j)
                    fma2(acc[i][j], ap[i], bp[j]);
        }
        __syncthreads();
        #pragma unroll
        for (int i = 0; i < 8; ++i)
            #pragma unroll
            for (int j = 0; j < 4; ++j) {
                float2 v = upk2(acc[i][j]);
                hid[(tm + 16 * i) * 129 + tq + 32 * j]      = fmaxf(v.x, 0.f);
                hid[(tm + 16 * i) * 129 + tq + 32 * j + 16] = fmaxf(v.y, 0.f);
            }
        __syncthreads();

        for (int idx = t; idx < 4096; idx += 256) wb[idx] = W2[idx];
        __syncthreads();

        // ---- stage 2: out = hid @ W2 + b2, f32x2 over column pair (tq,tq+16) ----
        unsigned long long acc2[8];
        {
            unsigned long long b = pk2(bb2[tq], bb2[tq + 16]);
            #pragma unroll
            for (int i = 0; i < 8; ++i) acc2[i] = b;
        }
        #pragma unroll 4
        for (int d = 0; d < 128; ++d) {
            unsigned long long bp = pk2(wb[d * 32 + tq], wb[d * 32 + tq + 16]);
            #pragma unroll
            for (int i = 0; i < 8; ++i) {
                float av = hid[(tm + 16 * i) * 129 + d];
                unsigned long long ap = pk2(av, av);
                fma2(acc2[i], ap, bp);
            }
        }
        float* H = f ? g_h2 : g_h1;
        #pragma unroll
        for (int i = 0; i < 8; ++i) {
            int node = base + tm + 16 * i;
            if (node < N) {
                float2 v = upk2(acc2[i]);
                H[node * 32 + tq]      = v.x;
                H[node * 32 + tq + 16] = v.y;
            }
        }
    }
}

// ----------------------------------------------------------------------------
// 4) warp-per-node gather + divide + InstanceNorm + residual ReLU (fused).
//    NO g_cnt writes here (see init_kernel note). x2 loop — measured 132us.
//    agg[i] = (sum_e s_e * h2[nbr]) / (1e-7 + sum_e s_e)  [denominator factored].
// ----------------------------------------------------------------------------
__device__ __forceinline__ float fast_sigmoid(float v) {
    float th;
    asm("tanh.approx.f32 %0, %1;" : "=f"(th) : "f"(0.5f * v));
    return fmaf(0.5f, th, 0.5f);
}

__global__ void __launch_bounds__(256) gather_kernel(
    const float* __restrict__ x,
    const float* __restrict__ ef,
    float* __restrict__ out, int N)
{
    int w    = (blockIdx.x * blockDim.x + threadIdx.x) >> 5;
    int lane = threadIdx.x & 31;
    if (w >= N) return;

    int deg = g_cnt[w];
    if (deg > CAP) deg = CAP;
    const int2* adj = &g_adj[w * CAP];
    float dsum = 0.f, nsum = 0.f;

    int k = 0;
    for (; k + 1 < deg; k += 2) {
        int2 c0 = adj[k];
        int2 c1 = adj[k + 1];
        float s0 = __ldcs(&ef[c0.y * 32 + lane]);
        float s1 = __ldcs(&ef[c1.y * 32 + lane]);
        float h0 = g_h2[c0.x * 32 + lane];
        float h1 = g_h2[c1.x * 32 + lane];
        s0 = fast_sigmoid(s0);
        s1 = fast_sigmoid(s1);
        dsum += s0 + s1;
        nsum = fmaf(s0, h0, nsum);
        nsum = fmaf(s1, h1, nsum);
    }
    if (k < deg) {
        int2 c0 = adj[k];
        float s0 = fast_sigmoid(__ldcs(&ef[c0.y * 32 + lane]));
        dsum += s0;
        nsum = fmaf(s0, g_h2[c0.x * 32 + lane], nsum);
    }

    float h = g_h1[w * 32 + lane] + nsum / (1e-7f + dsum);

    // InstanceNorm over the 32 feature lanes (biased variance, eps=1e-5)
    float mu = h;
    #pragma unroll
    for (int o = 16; o > 0; o >>= 1) mu += __shfl_xor_sync(0xffffffffu, mu, o);
    mu *= (1.f / 32.f);
    float df = h - mu;
    float vv = df * df;
    #pragma unroll
    for (int o = 16; o > 0; o >>= 1) vv += __shfl_xor_sync(0xffffffffu, vv, o);
    vv *= (1.f / 32.f);
    float hn = df * rsqrtf(vv + 1e-5f);

    out[w * 32 + lane] = x[w * 32 + lane] + fmaxf(hn, 0.f);
}

// ----------------------------------------------------------------------------
extern "C" void kernel_launch(void* const* d_in, const int* in_sizes, int n_in,
                              void* d_out, int out_size)
{
    const float* xin = (const float*)d_in[0];
    const float* ef  = (const float*)d_in[1];
    const float* W1a = (const float*)d_in[2];
    const float* b1a = (const float*)d_in[3];
    const float* W2a = (const float*)d_in[4];
    const float* b2a = (const float*)d_in[5];
    const float* W1b = (const float*)d_in[6];
    const float* b1b = (const float*)d_in[7];
    const float* W2b = (const float*)d_in[8];
    const float* b2b = (const float*)d_in[9];
    const void*  ei  = d_in[10];              // int32 or int64 — detected on device
    float* out = (float*)d_out;

    const int N = in_sizes[0] / 32;
    const int E = in_sizes[10] / 2;

    cudaFuncSetAttribute(fcnn_kernel,
                         cudaFuncAttributeMaxDynamicSharedMemorySize,
                         FCNN_SMEM_BYTES);

    init_kernel<<<(N + 255) / 256, 256>>>(ei, E, N);
    fill_kernel<<<(E + 255) / 256, 256>>>(ei, E, N);
    fcnn_kernel<<<(N + 127) / 128, 256, FCNN_SMEM_BYTES>>>(
        xin, W1a, b1a, W2a, b2a, W1b, b1b, W2b, b2b, N);
    gather_kernel<<<(N + 7) / 8, 256>>>(xin, ef, out, N);
}